// round 1
// baseline (speedup 1.0000x reference)
#include <cuda_runtime.h>

// Items: B*T = 1024*256 = 262144
// glb_reduced_6d: [BT, 10, 6] float  (d_in[0])
// orientation_6d: [BT, 6, 6]  float  (d_in[1])
// out:            [BT, 24, 3] float

__device__ __forceinline__ void gs6(const float* __restrict__ d, float* m) {
    // 6d -> 3x3 rotation (rows b1,b2,b3), row-major m[r*3+c]
    float x = d[0], y = d[1], z = d[2];
    float inv = rsqrtf(x * x + y * y + z * z);
    float b1x = x * inv, b1y = y * inv, b1z = z * inv;
    float u = d[3], v = d[4], w = d[5];
    float dot = b1x * u + b1y * v + b1z * w;
    float c2x = u - dot * b1x, c2y = v - dot * b1y, c2z = w - dot * b1z;
    float inv2 = rsqrtf(c2x * c2x + c2y * c2y + c2z * c2z);
    float b2x = c2x * inv2, b2y = c2y * inv2, b2z = c2z * inv2;
    float b3x = b1y * b2z - b1z * b2y;
    float b3y = b1z * b2x - b1x * b2z;
    float b3z = b1x * b2y - b1y * b2x;
    m[0] = b1x; m[1] = b1y; m[2] = b1z;
    m[3] = b2x; m[4] = b2y; m[5] = b2z;
    m[6] = b3x; m[7] = b3y; m[8] = b3z;
}

__device__ __forceinline__ void mm(const float* A, const float* B, float* C) {
    // C = A * B (3x3 row-major)
    #pragma unroll
    for (int r = 0; r < 3; r++)
        #pragma unroll
        for (int c = 0; c < 3; c++)
            C[r * 3 + c] = A[r * 3 + 0] * B[0 * 3 + c]
                         + A[r * 3 + 1] * B[1 * 3 + c]
                         + A[r * 3 + 2] * B[2 * 3 + c];
}

__device__ __forceinline__ void mmTN(const float* A, const float* B, float* C) {
    // C = A^T * B (3x3 row-major)
    #pragma unroll
    for (int r = 0; r < 3; r++)
        #pragma unroll
        for (int c = 0; c < 3; c++)
            C[r * 3 + c] = A[0 * 3 + r] * B[0 * 3 + c]
                         + A[1 * 3 + r] * B[1 * 3 + c]
                         + A[2 * 3 + r] * B[2 * 3 + c];
}

__device__ __forceinline__ void m2aa(const float* m, float* __restrict__ ob) {
    float m00 = m[0], m01 = m[1], m02 = m[2];
    float m10 = m[3], m11 = m[4], m12 = m[5];
    float m20 = m[6], m21 = m[7], m22 = m[8];
    float t0 = fmaxf(1.f + m00 + m11 + m22, 0.f);
    float t1 = fmaxf(1.f + m00 - m11 - m22, 0.f);
    float t2 = fmaxf(1.f - m00 + m11 - m22, 0.f);
    float t3 = fmaxf(1.f - m00 - m11 + m22, 0.f);
    // argmax over sqrt(t) == argmax over t (all >= 0); strict > keeps first on ties
    int idx = 0; float tb = t0;
    if (t1 > tb) { tb = t1; idx = 1; }
    if (t2 > tb) { tb = t2; idx = 2; }
    if (t3 > tb) { tb = t3; idx = 3; }
    float qa = sqrtf(tb);
    float qw, qx, qy, qz;
    if (idx == 0)      { qw = tb;        qx = m21 - m12; qy = m02 - m20; qz = m10 - m01; }
    else if (idx == 1) { qw = m21 - m12; qx = tb;        qy = m10 + m01; qz = m02 + m20; }
    else if (idx == 2) { qw = m02 - m20; qx = m10 + m01; qy = tb;        qz = m12 + m21; }
    else               { qw = m10 - m01; qx = m20 + m02; qy = m21 + m12; qz = tb;        }
    float invd = 1.f / (2.f * fmaxf(qa, 0.1f));
    qw *= invd; qx *= invd; qy *= invd; qz *= invd;
    float n = sqrtf(qx * qx + qy * qy + qz * qz);
    float half = atan2f(n, qw);
    float angle = 2.f * half;
    float s;
    if (fabsf(angle) < 1e-6f) s = 0.5f - angle * angle * (1.f / 48.f);
    else                      s = sinf(half) / angle;
    float invs = 1.f / s;
    ob[0] = qx * invs; ob[1] = qy * invs; ob[2] = qz * invs;
}

__global__ void __launch_bounds__(256)
pose_kernel(const float* __restrict__ glb, const float* __restrict__ ori,
            float* __restrict__ out, int n_items)
{
    int i = blockIdx.x * blockDim.x + threadIdx.x;
    if (i >= n_items) return;
    const float* g = glb + (long long)i * 60;
    const float* o = ori + (long long)i * 36;
    float* ob = out + (long long)i * 72;

    float root[9];
    gs6(o, root);
    m2aa(root, ob + 0);                      // joint 0

    float X[9], T[9], L[9];
    float G1[9], G2[9], G3[9], G6[9], G9[9];
    float G12[9], G13[9], G14[9], G16[9], G17[9];

    // joint 1..3: parent 0 (root)
    gs6(g + 0, X);  mm(root, X, G1);  mmTN(root, G1, L);  m2aa(L, ob + 3);
    gs6(g + 6, X);  mm(root, X, G2);  mmTN(root, G2, L);  m2aa(L, ob + 6);
    gs6(g + 12, X); mm(root, X, G3);  mmTN(root, G3, L);  m2aa(L, ob + 9);
    // joint 4 (sensor O1, parent 1), joint 5 (sensor O2, parent 2)
    gs6(o + 6, X);  mm(root, X, T);   mmTN(G1, T, L);     m2aa(L, ob + 12);
    gs6(o + 12, X); mm(root, X, T);   mmTN(G2, T, L);     m2aa(L, ob + 15);
    // joint 6 (R3, parent 3)
    gs6(g + 18, X); mm(root, X, G6);  mmTN(G3, G6, L);    m2aa(L, ob + 18);
    // joints 7,8 ignored -> zero
    ob[21] = 0.f; ob[22] = 0.f; ob[23] = 0.f;
    ob[24] = 0.f; ob[25] = 0.f; ob[26] = 0.f;
    // joint 9 (R4, parent 6)
    gs6(g + 24, X); mm(root, X, G9);  mmTN(G6, G9, L);    m2aa(L, ob + 27);
    // joints 10,11 ignored -> zero
    ob[30] = 0.f; ob[31] = 0.f; ob[32] = 0.f;
    ob[33] = 0.f; ob[34] = 0.f; ob[35] = 0.f;
    // joints 12,13,14 (R5,R6,R7; parent 9)
    gs6(g + 30, X); mm(root, X, G12); mmTN(G9, G12, L);   m2aa(L, ob + 36);
    gs6(g + 36, X); mm(root, X, G13); mmTN(G9, G13, L);   m2aa(L, ob + 39);
    gs6(g + 42, X); mm(root, X, G14); mmTN(G9, G14, L);   m2aa(L, ob + 42);
    // joint 15 (sensor O3, parent 12)
    gs6(o + 18, X); mm(root, X, T);   mmTN(G12, T, L);    m2aa(L, ob + 45);
    // joints 16,17 (R8,R9; parents 13,14)
    gs6(g + 48, X); mm(root, X, G16); mmTN(G13, G16, L);  m2aa(L, ob + 48);
    gs6(g + 54, X); mm(root, X, G17); mmTN(G14, G17, L);  m2aa(L, ob + 51);
    // joints 18,19 (sensors O4,O5; parents 16,17)
    gs6(o + 24, X); mm(root, X, T);   mmTN(G16, T, L);    m2aa(L, ob + 54);
    gs6(o + 30, X); mm(root, X, T);   mmTN(G17, T, L);    m2aa(L, ob + 57);
    // joints 20..23 ignored -> zero
    #pragma unroll
    for (int k = 60; k < 72; k++) ob[k] = 0.f;
}

extern "C" void kernel_launch(void* const* d_in, const int* in_sizes, int n_in,
                              void* d_out, int out_size) {
    const float* glb = (const float*)d_in[0];   // [BT,10,6]
    const float* ori = (const float*)d_in[1];   // [BT,6,6]
    float* out = (float*)d_out;                 // [BT,24,3]
    int n_items = in_sizes[0] / 60;
    int threads = 256;
    int blocks = (n_items + threads - 1) / threads;
    pose_kernel<<<blocks, threads>>>(glb, ori, out, n_items);
}

// round 2
// speedup vs baseline: 2.4949x; 2.4949x over previous
#include <cuda_runtime.h>

// glb_reduced_6d: [BT, 10, 6] float  (d_in[0])  -> 15 float4 per item (240B)
// orientation_6d: [BT, 6, 6]  float  (d_in[1])  ->  9 float4 per item (144B)
// out:            [BT, 24, 3] float              -> 18 float4 per item (288B)

__device__ __forceinline__ float fast_atan2p(float n, float w) {
    // atan2(n, w) with n >= 0; result in [0, pi]. ~1e-5 rad accuracy.
    float aw = fabsf(w);
    bool sw = n > aw;
    float num = sw ? aw : n;
    float den = sw ? n : aw;
    float r = __fdividef(num, den);
    float x2 = r * r;
    float p = -0.0117212f;
    p = fmaf(p, x2, 0.05265332f);
    p = fmaf(p, x2, -0.11643287f);
    p = fmaf(p, x2, 0.19354346f);
    p = fmaf(p, x2, -0.33262347f);
    p = fmaf(p, x2, 0.99997726f);
    float a = r * p;
    if (sw) a = 1.57079632679f - a;
    if (w < 0.f) a = 3.14159265359f - a;
    return a;
}

__device__ __forceinline__ void gs6(const float* __restrict__ d, float* __restrict__ m) {
    // 6d -> 3x3 rotation (rows b1,b2,b3), row-major
    float x = d[0], y = d[1], z = d[2];
    float inv = rsqrtf(x * x + y * y + z * z);
    float b1x = x * inv, b1y = y * inv, b1z = z * inv;
    float u = d[3], v = d[4], w = d[5];
    float dot = b1x * u + b1y * v + b1z * w;
    float c2x = u - dot * b1x, c2y = v - dot * b1y, c2z = w - dot * b1z;
    float inv2 = rsqrtf(c2x * c2x + c2y * c2y + c2z * c2z);
    float b2x = c2x * inv2, b2y = c2y * inv2, b2z = c2z * inv2;
    m[0] = b1x; m[1] = b1y; m[2] = b1z;
    m[3] = b2x; m[4] = b2y; m[5] = b2z;
    m[6] = b1y * b2z - b1z * b2y;
    m[7] = b1z * b2x - b1x * b2z;
    m[8] = b1x * b2y - b1y * b2x;
}

__device__ __forceinline__ void mmTN(const float* __restrict__ A, const float* __restrict__ B,
                                     float* __restrict__ C) {
    // C = A^T * B (3x3 row-major)
    #pragma unroll
    for (int r = 0; r < 3; r++)
        #pragma unroll
        for (int c = 0; c < 3; c++)
            C[r * 3 + c] = A[0 * 3 + r] * B[0 * 3 + c]
                         + A[1 * 3 + r] * B[1 * 3 + c]
                         + A[2 * 3 + r] * B[2 * 3 + c];
}

__device__ __forceinline__ void m2aa(const float* __restrict__ m, float* __restrict__ ob) {
    float m00 = m[0], m01 = m[1], m02 = m[2];
    float m10 = m[3], m11 = m[4], m12 = m[5];
    float m20 = m[6], m21 = m[7], m22 = m[8];
    float t0 = fmaxf(1.f + m00 + m11 + m22, 0.f);
    float t1 = fmaxf(1.f + m00 - m11 - m22, 0.f);
    float t2 = fmaxf(1.f - m00 + m11 - m22, 0.f);
    float t3 = fmaxf(1.f - m00 - m11 + m22, 0.f);
    int idx = 0; float tb = t0;
    if (t1 > tb) { tb = t1; idx = 1; }
    if (t2 > tb) { tb = t2; idx = 2; }
    if (t3 > tb) { tb = t3; idx = 3; }
    float qw, qx, qy, qz;
    if (idx == 0)      { qw = tb;        qx = m21 - m12; qy = m02 - m20; qz = m10 - m01; }
    else if (idx == 1) { qw = m21 - m12; qx = tb;        qy = m10 + m01; qz = m02 + m20; }
    else if (idx == 2) { qw = m02 - m20; qx = m10 + m01; qy = tb;        qz = m12 + m21; }
    else               { qw = m10 - m01; qx = m20 + m02; qy = m21 + m12; qz = tb;        }
    // Normalization 1/(2*max(qa,0.1)) cancels between q and sin(half)=|vec| (unit quat),
    // so out = vec_raw * (2*atan2(|vec_raw|, qw_raw) / |vec_raw|).
    float n = sqrtf(qx * qx + qy * qy + qz * qz);
    n = fmaxf(n, 1e-30f);
    float half = fast_atan2p(n, qw);
    float factor = __fdividef(2.f * half, n);
    ob[0] = qx * factor; ob[1] = qy * factor; ob[2] = qz * factor;
}

__device__ __forceinline__ void ld12(const float4* __restrict__ p, int i0, float* __restrict__ c) {
    float4 a = p[i0], b = p[i0 + 1], d = p[i0 + 2];
    c[0] = a.x; c[1] = a.y; c[2]  = a.z; c[3]  = a.w;
    c[4] = b.x; c[5] = b.y; c[6]  = b.z; c[7]  = b.w;
    c[8] = d.x; c[9] = d.y; c[10] = d.z; c[11] = d.w;
}

__global__ void __launch_bounds__(256)
pose_kernel(const float* __restrict__ glb, const float* __restrict__ ori,
            float* __restrict__ out, int n_items)
{
    int i = blockIdx.x * blockDim.x + threadIdx.x;
    if (i >= n_items) return;
    const float4* g4 = (const float4*)(glb + (size_t)i * 60);
    const float4* o4 = (const float4*)(ori + (size_t)i * 36);
    float4* ov = (float4*)(out + (size_t)i * 72);

    float buf[12];
    float c[12], c2[12];
    float Y1[9], Y2[9], Y3[9], Y6[9], Y9[9];
    float Y12[9], Y13[9], Y14[9], Y16[9], Y17[9];
    float W[9], L[9];
    float o3raw[6];

    // ---- Group A: joints 0..3 ----
    ld12(o4, 0, c);              // ori floats 0..11 (records O0, O1)
    gs6(c, W);                   // root
    m2aa(W, buf + 0);            // joint 0 (local = root)
    ld12(g4, 0, c2);             // glb floats 0..11 (records r0, r1)
    gs6(c2, Y1);     m2aa(Y1, buf + 3);   // joint 1 (local = Y1, root cancels)
    gs6(c2 + 6, Y2); m2aa(Y2, buf + 6);   // joint 2
    ld12(g4, 3, c2);             // glb floats 12..23 (records r2, r3)
    gs6(c2, Y3);     m2aa(Y3, buf + 9);   // joint 3
    ov[0] = make_float4(buf[0], buf[1], buf[2],  buf[3]);
    ov[1] = make_float4(buf[4], buf[5], buf[6],  buf[7]);
    ov[2] = make_float4(buf[8], buf[9], buf[10], buf[11]);

    // ---- Group B: joints 4,5,6,7 ----
    gs6(c + 6, W);               // O1 (ori floats 6..11)
    mmTN(Y1, W, L); m2aa(L, buf + 0);     // joint 4
    ld12(o4, 3, c);              // ori floats 12..23 (records O2, O3)
    gs6(c, W);                   // O2
    mmTN(Y2, W, L); m2aa(L, buf + 3);     // joint 5
    #pragma unroll
    for (int k = 0; k < 6; k++) o3raw[k] = c[6 + k];   // stash O3 raw
    gs6(c2 + 6, Y6);             // Y6 (glb floats 18..23)
    mmTN(Y3, Y6, L); m2aa(L, buf + 6);    // joint 6
    buf[9] = 0.f; buf[10] = 0.f; buf[11] = 0.f;        // joint 7 ignored
    ov[3] = make_float4(buf[0], buf[1], buf[2],  buf[3]);
    ov[4] = make_float4(buf[4], buf[5], buf[6],  buf[7]);
    ov[5] = make_float4(buf[8], buf[9], buf[10], buf[11]);

    // ---- Group C: joints 8,9,10,11 ----
    ld12(g4, 6, c2);             // glb floats 24..35 (records r4, r5)
    gs6(c2, Y9);
    mmTN(Y6, Y9, L); m2aa(L, buf + 3);    // joint 9
    buf[0] = 0.f; buf[1] = 0.f; buf[2] = 0.f;          // joint 8 ignored
    ov[6] = make_float4(buf[0], buf[1], buf[2], buf[3]);
    ov[7] = make_float4(buf[4], buf[5], 0.f, 0.f);     // j10 ignored
    ov[8] = make_float4(0.f, 0.f, 0.f, 0.f);           // j11 ignored

    // ---- Group D: joints 12,13,14,15 ----
    gs6(c2 + 6, Y12);
    mmTN(Y9, Y12, L); m2aa(L, buf + 0);   // joint 12
    ld12(g4, 9, c2);             // glb floats 36..47 (records r6, r7)
    gs6(c2, Y13);
    mmTN(Y9, Y13, L); m2aa(L, buf + 3);   // joint 13
    gs6(c2 + 6, Y14);
    mmTN(Y9, Y14, L); m2aa(L, buf + 6);   // joint 14
    gs6(o3raw, W);               // O3
    mmTN(Y12, W, L); m2aa(L, buf + 9);    // joint 15
    ov[9]  = make_float4(buf[0], buf[1], buf[2],  buf[3]);
    ov[10] = make_float4(buf[4], buf[5], buf[6],  buf[7]);
    ov[11] = make_float4(buf[8], buf[9], buf[10], buf[11]);

    // ---- Group E: joints 16,17,18,19 ----
    ld12(g4, 12, c2);            // glb floats 48..59 (records r8, r9)
    gs6(c2, Y16);
    mmTN(Y13, Y16, L); m2aa(L, buf + 0);  // joint 16
    gs6(c2 + 6, Y17);
    mmTN(Y14, Y17, L); m2aa(L, buf + 3);  // joint 17
    ld12(o4, 6, c);              // ori floats 24..35 (records O4, O5)
    gs6(c, W);                   // O4
    mmTN(Y16, W, L); m2aa(L, buf + 6);    // joint 18
    gs6(c + 6, W);               // O5
    mmTN(Y17, W, L); m2aa(L, buf + 9);    // joint 19
    ov[12] = make_float4(buf[0], buf[1], buf[2],  buf[3]);
    ov[13] = make_float4(buf[4], buf[5], buf[6],  buf[7]);
    ov[14] = make_float4(buf[8], buf[9], buf[10], buf[11]);

    // ---- Group F: joints 20..23 ignored ----
    float4 z = make_float4(0.f, 0.f, 0.f, 0.f);
    ov[15] = z; ov[16] = z; ov[17] = z;
}

extern "C" void kernel_launch(void* const* d_in, const int* in_sizes, int n_in,
                              void* d_out, int out_size) {
    const float* glb = (const float*)d_in[0];   // [BT,10,6]
    const float* ori = (const float*)d_in[1];   // [BT,6,6]
    float* out = (float*)d_out;                 // [BT,24,3]
    int n_items = in_sizes[0] / 60;
    int threads = 256;
    int blocks = (n_items + threads - 1) / threads;
    pose_kernel<<<blocks, threads>>>(glb, ori, out, n_items);
}

// round 5
// speedup vs baseline: 2.7773x; 1.1132x over previous
#include <cuda_runtime.h>

// glb_reduced_6d: [BT, 10, 6] float (d_in[0]) -> 60 floats/item, contiguous
// orientation_6d: [BT, 6, 6]  float (d_in[1]) -> 36 floats/item
// out:            [BT, 24, 3] float           -> 72 floats/item

#define WARPS_PER_BLOCK 3
#define STRIDE 97   // floats per item slot; odd -> conflict-free per-lane LDS

__device__ __forceinline__ float fast_atan2p(float n, float w) {
    // atan2(n, w) with n >= 0; result in [0, pi]. ~1e-5 rad accuracy.
    float aw = fabsf(w);
    bool sw = n > aw;
    float num = sw ? aw : n;
    float den = sw ? n : aw;
    float r = __fdividef(num, den);
    float x2 = r * r;
    float p = -0.0117212f;
    p = fmaf(p, x2, 0.05265332f);
    p = fmaf(p, x2, -0.11643287f);
    p = fmaf(p, x2, 0.19354346f);
    p = fmaf(p, x2, -0.33262347f);
    p = fmaf(p, x2, 0.99997726f);
    float a = r * p;
    if (sw) a = 1.57079632679f - a;
    if (w < 0.f) a = 3.14159265359f - a;
    return a;
}

__device__ __forceinline__ void gs6(const float* d, float* __restrict__ m) {
    float x = d[0], y = d[1], z = d[2];
    float inv = rsqrtf(x * x + y * y + z * z);
    float b1x = x * inv, b1y = y * inv, b1z = z * inv;
    float u = d[3], v = d[4], w = d[5];
    float dot = b1x * u + b1y * v + b1z * w;
    float c2x = u - dot * b1x, c2y = v - dot * b1y, c2z = w - dot * b1z;
    float inv2 = rsqrtf(c2x * c2x + c2y * c2y + c2z * c2z);
    float b2x = c2x * inv2, b2y = c2y * inv2, b2z = c2z * inv2;
    m[0] = b1x; m[1] = b1y; m[2] = b1z;
    m[3] = b2x; m[4] = b2y; m[5] = b2z;
    m[6] = b1y * b2z - b1z * b2y;
    m[7] = b1z * b2x - b1x * b2z;
    m[8] = b1x * b2y - b1y * b2x;
}

__device__ __forceinline__ void mmTN(const float* __restrict__ A, const float* __restrict__ B,
                                     float* __restrict__ C) {
    #pragma unroll
    for (int r = 0; r < 3; r++)
        #pragma unroll
        for (int c = 0; c < 3; c++)
            C[r * 3 + c] = A[0 * 3 + r] * B[0 * 3 + c]
                         + A[1 * 3 + r] * B[1 * 3 + c]
                         + A[2 * 3 + r] * B[2 * 3 + c];
}

__device__ __forceinline__ void m2aa(const float* __restrict__ m, float* ob) {
    float m00 = m[0], m01 = m[1], m02 = m[2];
    float m10 = m[3], m11 = m[4], m12 = m[5];
    float m20 = m[6], m21 = m[7], m22 = m[8];
    float t0 = fmaxf(1.f + m00 + m11 + m22, 0.f);
    float t1 = fmaxf(1.f + m00 - m11 - m22, 0.f);
    float t2 = fmaxf(1.f - m00 + m11 - m22, 0.f);
    float t3 = fmaxf(1.f - m00 - m11 + m22, 0.f);
    int idx = 0; float tb = t0;
    if (t1 > tb) { tb = t1; idx = 1; }
    if (t2 > tb) { tb = t2; idx = 2; }
    if (t3 > tb) { tb = t3; idx = 3; }
    float qw, qx, qy, qz;
    if (idx == 0)      { qw = tb;        qx = m21 - m12; qy = m02 - m20; qz = m10 - m01; }
    else if (idx == 1) { qw = m21 - m12; qx = tb;        qy = m10 + m01; qz = m02 + m20; }
    else if (idx == 2) { qw = m02 - m20; qx = m10 + m01; qy = tb;        qz = m12 + m21; }
    else               { qw = m10 - m01; qx = m20 + m02; qy = m21 + m12; qz = tb;        }
    // 1/(2*max(qa,0.1)) cancels (unit quat: sin(half)=|vec|):
    // out = vec_raw * (2*atan2(|vec_raw|, qw_raw) / |vec_raw|)
    float n = sqrtf(qx * qx + qy * qy + qz * qz);
    n = fmaxf(n, 1e-30f);
    float half = fast_atan2p(n, qw);
    float factor = __fdividef(2.f * half, n);
    ob[0] = qx * factor; ob[1] = qy * factor; ob[2] = qz * factor;
}

__global__ void __launch_bounds__(32 * WARPS_PER_BLOCK, 6)
pose_kernel(const float* __restrict__ glb, const float* __restrict__ ori,
            float* __restrict__ out, int n_items)
{
    __shared__ float sm[WARPS_PER_BLOCK * 32 * STRIDE];
    int warp = threadIdx.x >> 5;
    int lane = threadIdx.x & 31;
    int base = (blockIdx.x * WARPS_PER_BLOCK + warp) * 32;
    float* ws = sm + warp * 32 * STRIDE;
    int cnt = n_items - base;
    if (cnt > 32) cnt = 32;
    if (cnt < 0) cnt = 0;

    // ---- Stage glb: 32 items x 60 floats contiguous, coalesced float4 ----
    {
        const float4* src = (const float4*)(glb + (size_t)base * 60);
        int ntot = cnt * 15;
        #pragma unroll
        for (int k = 0; k < 15; k++) {
            int j = k * 32 + lane;
            if (j < ntot) {
                float4 v = src[j];
                float* p = ws + (j / 15) * STRIDE + (j % 15) * 4;
                p[0] = v.x; p[1] = v.y; p[2] = v.z; p[3] = v.w;
            }
        }
    }
    // ---- Stage ori: 32 items x 36 floats, coalesced float4, at slot offset 60 ----
    {
        const float4* src = (const float4*)(ori + (size_t)base * 36);
        int ntot = cnt * 9;
        #pragma unroll
        for (int k = 0; k < 9; k++) {
            int j = k * 32 + lane;
            if (j < ntot) {
                float4 v = src[j];
                float* p = ws + (j / 9) * STRIDE + 60 + (j % 9) * 4;
                p[0] = v.x; p[1] = v.y; p[2] = v.z; p[3] = v.w;
            }
        }
    }
    __syncwarp();

    // ---- Compute: lane owns item base+lane; its slot holds inputs, then outputs.
    // Slot map: glb at my[0..59], ori at my[60..95]; outputs at my[0..71].
    // Every output store happens only after the aliased input float was consumed.
    if (lane < cnt) {
        float* my = ws + lane * STRIDE;
        float Y1[9], Y2[9], Y3[9], Y6[9], Y9[9];
        float Y12[9], Y13[9], Y14[9], Y16[9], Y17[9];
        float W[9], L[9];

        gs6(my + 0,  Y1);                    // glb 0..5
        gs6(my + 6,  Y2);                    // glb 6..11
        gs6(my + 12, Y3);                    // glb 12..17
        gs6(my + 60, W);                     // root (ori 0..5)
        m2aa(W,  my + 0);                    // joint 0
        m2aa(Y1, my + 3);                    // joint 1
        m2aa(Y2, my + 6);                    // joint 2
        m2aa(Y3, my + 9);                    // joint 3

        gs6(my + 66, W);                     // O1 (ori 6..11)
        mmTN(Y1, W, L); m2aa(L, my + 12);    // joint 4
        gs6(my + 72, W);                     // O2 (ori 12..17)
        mmTN(Y2, W, L); m2aa(L, my + 15);    // joint 5

        gs6(my + 18, Y6);                    // glb 18..23
        mmTN(Y3, Y6, L); m2aa(L, my + 18);   // joint 6
        my[21] = 0.f; my[22] = 0.f; my[23] = 0.f;   // joint 7

        gs6(my + 24, Y9);                    // glb 24..29 (read BEFORE j8 zeros)
        my[24] = 0.f; my[25] = 0.f; my[26] = 0.f;   // joint 8
        mmTN(Y6, Y9, L); m2aa(L, my + 27);   // joint 9

        gs6(my + 30, Y12);                   // glb 30..35 (read BEFORE j10/j11 zeros)
        my[30] = 0.f; my[31] = 0.f; my[32] = 0.f;   // joint 10
        my[33] = 0.f; my[34] = 0.f; my[35] = 0.f;   // joint 11
        gs6(my + 36, Y13);                   // glb 36..41 (read BEFORE j12/j13 out)
        mmTN(Y9, Y12, L); m2aa(L, my + 36);  // joint 12
        mmTN(Y9, Y13, L); m2aa(L, my + 39);  // joint 13
        gs6(my + 42, Y14);                   // glb 42..47
        mmTN(Y9, Y14, L); m2aa(L, my + 42);  // joint 14
        gs6(my + 78, W);                     // O3 (ori 18..23)
        mmTN(Y12, W, L); m2aa(L, my + 45);   // joint 15

        gs6(my + 48, Y16);                   // glb 48..53
        mmTN(Y13, Y16, L); m2aa(L, my + 48); // joint 16
        gs6(my + 54, Y17);                   // glb 54..59 (read BEFORE j17 out)
        mmTN(Y14, Y17, L); m2aa(L, my + 51); // joint 17
        gs6(my + 84, W);                     // O4 (ori 24..29)
        mmTN(Y16, W, L); m2aa(L, my + 54);   // joint 18
        gs6(my + 90, W);                     // O5 (ori 30..35)
        mmTN(Y17, W, L); m2aa(L, my + 57);   // joint 19
        #pragma unroll
        for (int k = 60; k < 72; k++) my[k] = 0.f;  // joints 20..23
    }
    __syncwarp();

    // ---- Coalesced float4 stores: 32 items x 72 floats contiguous ----
    {
        float4* dst = (float4*)(out + (size_t)base * 72);
        int ntot = cnt * 18;
        #pragma unroll
        for (int k = 0; k < 18; k++) {
            int j = k * 32 + lane;
            if (j < ntot) {
                const float* p = ws + (j / 18) * STRIDE + (j % 18) * 4;
                dst[j] = make_float4(p[0], p[1], p[2], p[3]);
            }
        }
    }
}

extern "C" void kernel_launch(void* const* d_in, const int* in_sizes, int n_in,
                              void* d_out, int out_size) {
    const float* glb = (const float*)d_in[0];   // [BT,10,6]
    const float* ori = (const float*)d_in[1];   // [BT,6,6]
    float* out = (float*)d_out;                 // [BT,24,3]
    int n_items = in_sizes[0] / 60;
    int items_per_block = 32 * WARPS_PER_BLOCK;
    int blocks = (n_items + items_per_block - 1) / items_per_block;
    pose_kernel<<<blocks, 32 * WARPS_PER_BLOCK>>>(glb, ori, out, n_items);
}

// round 6
// speedup vs baseline: 2.8139x; 1.0132x over previous
#include <cuda_runtime.h>

// glb_reduced_6d: [BT, 10, 6] float (d_in[0]) -> 60 floats/item
// orientation_6d: [BT, 6, 6]  float (d_in[1]) -> 36 floats/item
// out:            [BT, 24, 3] float           -> 72 floats/item
//
// Block = 128 threads / 64 items. Warp w: role = w&1, items (w>>1)*32 + lane.
// Role 0 computes joints {0,1,2,3,6,9,12,13,14,15}; role 1 computes {4,5,16,17,18,19}.
// Compute phase is read-only on smem; all smem writes happen after a barrier.

#define STRIDE 97           // floats per item slot; odd -> conflict-free LDS
#define ITEMS_PER_BLOCK 64
#define THREADS 128

__device__ __forceinline__ float fast_atan2p(float n, float w) {
    // atan2(n, w) with n >= 0; result in [0, pi]. ~1e-5 rad accuracy.
    float aw = fabsf(w);
    bool sw = n > aw;
    float num = sw ? aw : n;
    float den = sw ? n : aw;
    float r = __fdividef(num, den);
    float x2 = r * r;
    float p = -0.0117212f;
    p = fmaf(p, x2, 0.05265332f);
    p = fmaf(p, x2, -0.11643287f);
    p = fmaf(p, x2, 0.19354346f);
    p = fmaf(p, x2, -0.33262347f);
    p = fmaf(p, x2, 0.99997726f);
    float a = r * p;
    if (sw) a = 1.57079632679f - a;
    if (w < 0.f) a = 3.14159265359f - a;
    return a;
}

__device__ __forceinline__ void gs6(const float* d, float* __restrict__ m) {
    float x = d[0], y = d[1], z = d[2];
    float inv = rsqrtf(x * x + y * y + z * z);
    float b1x = x * inv, b1y = y * inv, b1z = z * inv;
    float u = d[3], v = d[4], w = d[5];
    float dot = b1x * u + b1y * v + b1z * w;
    float c2x = u - dot * b1x, c2y = v - dot * b1y, c2z = w - dot * b1z;
    float inv2 = rsqrtf(c2x * c2x + c2y * c2y + c2z * c2z);
    float b2x = c2x * inv2, b2y = c2y * inv2, b2z = c2z * inv2;
    m[0] = b1x; m[1] = b1y; m[2] = b1z;
    m[3] = b2x; m[4] = b2y; m[5] = b2z;
    m[6] = b1y * b2z - b1z * b2y;
    m[7] = b1z * b2x - b1x * b2z;
    m[8] = b1x * b2y - b1y * b2x;
}

__device__ __forceinline__ void mmTN(const float* __restrict__ A, const float* __restrict__ B,
                                     float* __restrict__ C) {
    #pragma unroll
    for (int r = 0; r < 3; r++)
        #pragma unroll
        for (int c = 0; c < 3; c++)
            C[r * 3 + c] = A[0 * 3 + r] * B[0 * 3 + c]
                         + A[1 * 3 + r] * B[1 * 3 + c]
                         + A[2 * 3 + r] * B[2 * 3 + c];
}

__device__ __forceinline__ void m2aa(const float* __restrict__ m, float* __restrict__ ob) {
    float m00 = m[0], m01 = m[1], m02 = m[2];
    float m10 = m[3], m11 = m[4], m12 = m[5];
    float m20 = m[6], m21 = m[7], m22 = m[8];
    float t0 = fmaxf(1.f + m00 + m11 + m22, 0.f);
    float t1 = fmaxf(1.f + m00 - m11 - m22, 0.f);
    float t2 = fmaxf(1.f - m00 + m11 - m22, 0.f);
    float t3 = fmaxf(1.f - m00 - m11 + m22, 0.f);
    int idx = 0; float tb = t0;
    if (t1 > tb) { tb = t1; idx = 1; }
    if (t2 > tb) { tb = t2; idx = 2; }
    if (t3 > tb) { tb = t3; idx = 3; }
    float qw, qx, qy, qz;
    if (idx == 0)      { qw = tb;        qx = m21 - m12; qy = m02 - m20; qz = m10 - m01; }
    else if (idx == 1) { qw = m21 - m12; qx = tb;        qy = m10 + m01; qz = m02 + m20; }
    else if (idx == 2) { qw = m02 - m20; qx = m10 + m01; qy = tb;        qz = m12 + m21; }
    else               { qw = m10 - m01; qx = m20 + m02; qy = m21 + m12; qz = tb;        }
    // 1/(2*max(qa,0.1)) cancels (unit quat: sin(half)=|vec|):
    // out = vec_raw * (2*atan2(|vec_raw|, qw_raw) / |vec_raw|)
    float n = sqrtf(qx * qx + qy * qy + qz * qz);
    n = fmaxf(n, 1e-30f);
    float half = fast_atan2p(n, qw);
    float factor = __fdividef(2.f * half, n);
    ob[0] = qx * factor; ob[1] = qy * factor; ob[2] = qz * factor;
}

__global__ void __launch_bounds__(THREADS, 7)
pose_kernel(const float* __restrict__ glb, const float* __restrict__ ori,
            float* __restrict__ out, int n_items)
{
    __shared__ float sm[ITEMS_PER_BLOCK * STRIDE];
    const int tid = threadIdx.x;
    const int warp = tid >> 5;
    const int lane = tid & 31;
    const int base = blockIdx.x * ITEMS_PER_BLOCK;
    int cnt = n_items - base;
    if (cnt > ITEMS_PER_BLOCK) cnt = ITEMS_PER_BLOCK;
    if (cnt < 0) cnt = 0;

    // ---- Stage glb: 64 items x 15 f4, coalesced; slot floats [0..59] ----
    {
        const float4* src = (const float4*)(glb + (size_t)base * 60);
        int ntot = cnt * 15;
        for (int j = tid; j < ntot; j += THREADS) {
            float4 v = src[j];
            float* p = sm + (j / 15) * STRIDE + (j % 15) * 4;
            p[0] = v.x; p[1] = v.y; p[2] = v.z; p[3] = v.w;
        }
    }
    // ---- Stage ori: 64 items x 9 f4; slot floats [60..95] ----
    // record r at slot offset 60+6r: root=60, O1=66, O2=72, O3=78, O4=84, O5=90
    {
        const float4* src = (const float4*)(ori + (size_t)base * 36);
        int ntot = cnt * 9;
        for (int j = tid; j < ntot; j += THREADS) {
            float4 v = src[j];
            float* p = sm + (j / 9) * STRIDE + 60 + (j % 9) * 4;
            p[0] = v.x; p[1] = v.y; p[2] = v.z; p[3] = v.w;
        }
    }
    __syncthreads();

    const int role = warp & 1;
    const int item_local = (warp >> 1) * 32 + lane;
    float* my = sm + item_local * STRIDE;
    const bool valid = item_local < cnt;

    // ---- Compute phase: smem READ-ONLY; results accumulate in registers ----
    float res[30];
    if (valid) {
        float A[9], Bm[9], C[9], L[9];
        if (role == 0) {
            gs6(my + 60, A);  m2aa(A, res + 0);     // joint 0 (root)
            gs6(my + 0,  A);  m2aa(A, res + 3);     // joint 1 (Y1)
            gs6(my + 6,  A);  m2aa(A, res + 6);     // joint 2 (Y2)
            gs6(my + 12, A);  m2aa(A, res + 9);     // joint 3 (Y3, kept)
            gs6(my + 18, Bm);                       // Y6
            mmTN(A, Bm, L);  m2aa(L, res + 12);     // joint 6  = Y3^T Y6
            gs6(my + 24, A);                        // Y9
            mmTN(Bm, A, L);  m2aa(L, res + 15);     // joint 9  = Y6^T Y9
            gs6(my + 30, Bm);                       // Y12
            mmTN(A, Bm, L);  m2aa(L, res + 18);     // joint 12 = Y9^T Y12
            gs6(my + 36, C);                        // Y13
            mmTN(A, C, L);   m2aa(L, res + 21);     // joint 13 = Y9^T Y13
            gs6(my + 42, C);                        // Y14
            mmTN(A, C, L);   m2aa(L, res + 24);     // joint 14 = Y9^T Y14
            gs6(my + 78, C);                        // O3
            mmTN(Bm, C, L);  m2aa(L, res + 27);     // joint 15 = Y12^T O3
        } else {
            gs6(my + 0,  A); gs6(my + 66, Bm);      // Y1, O1
            mmTN(A, Bm, L);  m2aa(L, res + 0);      // joint 4  = Y1^T O1
            gs6(my + 6,  A); gs6(my + 72, Bm);      // Y2, O2
            mmTN(A, Bm, L);  m2aa(L, res + 3);      // joint 5  = Y2^T O2
            gs6(my + 36, A); gs6(my + 48, Bm);      // Y13, Y16 (Y16 kept)
            mmTN(A, Bm, L);  m2aa(L, res + 6);      // joint 16 = Y13^T Y16
            gs6(my + 54, A);                        // Y17 (kept)
            gs6(my + 42, C);                        // Y14
            mmTN(C, A, L);   m2aa(L, res + 9);      // joint 17 = Y14^T Y17
            gs6(my + 84, C);                        // O4
            mmTN(Bm, C, L);  m2aa(L, res + 12);     // joint 18 = Y16^T O4
            gs6(my + 90, C);                        // O5
            mmTN(A, C, L);   m2aa(L, res + 15);     // joint 19 = Y17^T O5
        }
    }
    __syncthreads();   // every thread's input reads are complete

    // ---- Store phase: disjoint smem writes per role ----
    if (valid) {
        if (role == 0) {
            #pragma unroll
            for (int k = 0; k < 12; k++) my[k] = res[k];       // joints 0..3
            my[18] = res[12]; my[19] = res[13]; my[20] = res[14];  // joint 6
            my[21] = 0.f; my[22] = 0.f; my[23] = 0.f;          // joint 7
            my[24] = 0.f; my[25] = 0.f; my[26] = 0.f;          // joint 8
            my[27] = res[15]; my[28] = res[16]; my[29] = res[17];  // joint 9
            my[30] = 0.f; my[31] = 0.f; my[32] = 0.f;          // joint 10
            my[33] = 0.f; my[34] = 0.f; my[35] = 0.f;          // joint 11
            #pragma unroll
            for (int k = 0; k < 12; k++) my[36 + k] = res[18 + k]; // joints 12..15
        } else {
            my[12] = res[0];  my[13] = res[1];  my[14] = res[2];   // joint 4
            my[15] = res[3];  my[16] = res[4];  my[17] = res[5];   // joint 5
            my[48] = res[6];  my[49] = res[7];  my[50] = res[8];   // joint 16
            my[51] = res[9];  my[52] = res[10]; my[53] = res[11];  // joint 17
            my[54] = res[12]; my[55] = res[13]; my[56] = res[14];  // joint 18
            my[57] = res[15]; my[58] = res[16]; my[59] = res[17];  // joint 19
        }
    }
    __syncthreads();

    // ---- Coalesced f4 stores; output chunks 15..17 (joints 20..23) are zero ----
    {
        float4* dst = (float4*)(out + (size_t)base * 72);
        int ntot = cnt * 18;
        for (int j = tid; j < ntot; j += THREADS) {
            int c = j % 18;
            if (c >= 15) {
                dst[j] = make_float4(0.f, 0.f, 0.f, 0.f);
            } else {
                const float* p = sm + (j / 18) * STRIDE + c * 4;
                dst[j] = make_float4(p[0], p[1], p[2], p[3]);
            }
        }
    }
}

extern "C" void kernel_launch(void* const* d_in, const int* in_sizes, int n_in,
                              void* d_out, int out_size) {
    const float* glb = (const float*)d_in[0];   // [BT,10,6]
    const float* ori = (const float*)d_in[1];   // [BT,6,6]
    float* out = (float*)d_out;                 // [BT,24,3]
    int n_items = in_sizes[0] / 60;
    int blocks = (n_items + ITEMS_PER_BLOCK - 1) / ITEMS_PER_BLOCK;
    pose_kernel<<<blocks, THREADS>>>(glb, ori, out, n_items);
}

// round 10
// speedup vs baseline: 3.2132x; 1.1419x over previous
#include <cuda_runtime.h>

// glb_reduced_6d: [BT, 10, 6] float (d_in[0]) -> 60 floats/item
// orientation_6d: [BT, 6, 6]  float (d_in[1]) -> 36 floats/item
// out:            [BT, 24, 3] float           -> 72 floats/item
//
// Block = 128 threads / 64 items. Warp w: role = w&1, item = (w>>1)*32 + lane.
// Role 0: joints {0,1,2,3,6,9,12,13,14,15}; role 1: {4,5,16,17,18,19} + tail zeros.
// Slot stride 98 floats: 8B-aligned slots, even offsets -> LDS.64, conflict-free
// (98 mod 32 = 2: within a 16-lane wavefront phase banks are distinct).

#define STRIDE 98
#define ITEMS_PER_BLOCK 64
#define THREADS 128

__device__ __forceinline__ float fast_atan2p(float n, float w) {
    // atan2(n, w) with n >= 0; result in [0, pi]. ~1e-5 rad accuracy.
    float aw = fabsf(w);
    bool sw = n > aw;
    float num = sw ? aw : n;
    float den = sw ? n : aw;
    float r = __fdividef(num, den);
    float x2 = r * r;
    float p = -0.0117212f;
    p = fmaf(p, x2, 0.05265332f);
    p = fmaf(p, x2, -0.11643287f);
    p = fmaf(p, x2, 0.19354346f);
    p = fmaf(p, x2, -0.33262347f);
    p = fmaf(p, x2, 0.99997726f);
    float a = r * p;
    if (sw) a = 1.57079632679f - a;
    if (w < 0.f) a = 3.14159265359f - a;
    return a;
}

// d must be 8-byte aligned (even float offset in an 8B-aligned slot)
__device__ __forceinline__ void gs6(const float* d, float* __restrict__ m) {
    const float2* q = (const float2*)d;
    float2 q0 = q[0], q1 = q[1], q2 = q[2];
    float x = q0.x, y = q0.y, z = q1.x;
    float u = q1.y, v = q2.x, w = q2.y;
    float inv = rsqrtf(x * x + y * y + z * z);
    float b1x = x * inv, b1y = y * inv, b1z = z * inv;
    float dot = b1x * u + b1y * v + b1z * w;
    float c2x = u - dot * b1x, c2y = v - dot * b1y, c2z = w - dot * b1z;
    float inv2 = rsqrtf(c2x * c2x + c2y * c2y + c2z * c2z);
    float b2x = c2x * inv2, b2y = c2y * inv2, b2z = c2z * inv2;
    m[0] = b1x; m[1] = b1y; m[2] = b1z;
    m[3] = b2x; m[4] = b2y; m[5] = b2z;
    m[6] = b1y * b2z - b1z * b2y;
    m[7] = b1z * b2x - b1x * b2z;
    m[8] = b1x * b2y - b1y * b2x;
}

__device__ __forceinline__ void mmTN(const float* __restrict__ A, const float* __restrict__ B,
                                     float* __restrict__ C) {
    #pragma unroll
    for (int r = 0; r < 3; r++)
        #pragma unroll
        for (int c = 0; c < 3; c++)
            C[r * 3 + c] = A[0 * 3 + r] * B[0 * 3 + c]
                         + A[1 * 3 + r] * B[1 * 3 + c]
                         + A[2 * 3 + r] * B[2 * 3 + c];
}

__device__ __forceinline__ void m2aa(const float* __restrict__ m, float* __restrict__ ob) {
    float m00 = m[0], m01 = m[1], m02 = m[2];
    float m10 = m[3], m11 = m[4], m12 = m[5];
    float m20 = m[6], m21 = m[7], m22 = m[8];
    float t0 = fmaxf(1.f + m00 + m11 + m22, 0.f);
    float t1 = fmaxf(1.f + m00 - m11 - m22, 0.f);
    float t2 = fmaxf(1.f - m00 + m11 - m22, 0.f);
    float t3 = fmaxf(1.f - m00 - m11 + m22, 0.f);
    // Branchless 2-level argmax tournament; strict > preserves reference's
    // first-max-on-tie semantics (argmax).
    bool a01 = t1 > t0;            // winner of {0,1}: prefers 0
    bool a23 = t3 > t2;            // winner of {2,3}: prefers 2
    float ta = a01 ? t1 : t0;
    float tc = a23 ? t3 : t2;
    bool ab  = tc > ta;            // prefers {0,1} pair
    float tb = ab ? tc : ta;
    float qw = ab ? (a23 ? m10 - m01 : m02 - m20) : (a01 ? m21 - m12 : t0);
    float qx = ab ? (a23 ? m20 + m02 : m10 + m01) : (a01 ? t1        : m21 - m12);
    float qy = ab ? (a23 ? m21 + m12 : t2       ) : (a01 ? m10 + m01 : m02 - m20);
    float qz = ab ? (a23 ? t3        : m12 + m21) : (a01 ? m02 + m20 : m10 - m01);
    (void)tb;
    // 1/(2*max(qa,0.1)) cancels (unit quat: sin(half)=|vec|):
    // out = vec_raw * (2*atan2(|vec_raw|, qw_raw) / |vec_raw|)
    float n = sqrtf(qx * qx + qy * qy + qz * qz);
    n = fmaxf(n, 1e-30f);
    float half = fast_atan2p(n, qw);
    float factor = __fdividef(2.f * half, n);
    ob[0] = qx * factor; ob[1] = qy * factor; ob[2] = qz * factor;
}

__global__ void __launch_bounds__(THREADS, 5)
pose_kernel(const float* __restrict__ glb, const float* __restrict__ ori,
            float* __restrict__ out, int n_items)
{
    __shared__ float sm[ITEMS_PER_BLOCK * STRIDE];
    const int tid = threadIdx.x;
    const int warp = tid >> 5;
    const int lane = tid & 31;
    const int base = blockIdx.x * ITEMS_PER_BLOCK;
    int cnt = n_items - base;
    if (cnt > ITEMS_PER_BLOCK) cnt = ITEMS_PER_BLOCK;
    if (cnt < 0) cnt = 0;

    // ---- Stage glb: 64 items x 15 f4, coalesced; slot floats [0..59] ----
    {
        const float4* src = (const float4*)(glb + (size_t)base * 60);
        int ntot = cnt * 15;
        #pragma unroll
        for (int k = 0; k < 8; k++) {
            int j = k * THREADS + tid;
            if (j < ntot) {
                float4 v = src[j];
                float2* p = (float2*)(sm + (j / 15) * STRIDE + (j % 15) * 4);
                p[0] = make_float2(v.x, v.y);
                p[1] = make_float2(v.z, v.w);
            }
        }
    }
    // ---- Stage ori: 64 items x 9 f4; slot floats [60..95] ----
    {
        const float4* src = (const float4*)(ori + (size_t)base * 36);
        int ntot = cnt * 9;
        #pragma unroll
        for (int k = 0; k < 5; k++) {
            int j = k * THREADS + tid;
            if (j < ntot) {
                float4 v = src[j];
                float2* p = (float2*)(sm + (j / 9) * STRIDE + 60 + (j % 9) * 4);
                p[0] = make_float2(v.x, v.y);
                p[1] = make_float2(v.z, v.w);
            }
        }
    }
    __syncthreads();

    const int role = warp & 1;
    const int item_local = (warp >> 1) * 32 + lane;
    float* my = sm + item_local * STRIDE;
    const bool valid = item_local < cnt;

    // ---- Compute phase: smem READ-ONLY; results in registers ----
    float res[30];
    if (valid) {
        float A[9], Bm[9], C[9], L[9];
        if (role == 0) {
            gs6(my + 60, A);  m2aa(A, res + 0);     // joint 0 (root)
            gs6(my + 0,  A);  m2aa(A, res + 3);     // joint 1 (Y1)
            gs6(my + 6,  A);  m2aa(A, res + 6);     // joint 2 (Y2)
            gs6(my + 12, A);  m2aa(A, res + 9);     // joint 3 (Y3, kept)
            gs6(my + 18, Bm);                       // Y6
            mmTN(A, Bm, L);  m2aa(L, res + 12);     // joint 6  = Y3^T Y6
            gs6(my + 24, A);                        // Y9
            mmTN(Bm, A, L);  m2aa(L, res + 15);     // joint 9  = Y6^T Y9
            gs6(my + 30, Bm);                       // Y12
            mmTN(A, Bm, L);  m2aa(L, res + 18);     // joint 12 = Y9^T Y12
            gs6(my + 36, C);                        // Y13
            mmTN(A, C, L);   m2aa(L, res + 21);     // joint 13 = Y9^T Y13
            gs6(my + 42, C);                        // Y14
            mmTN(A, C, L);   m2aa(L, res + 24);     // joint 14 = Y9^T Y14
            gs6(my + 78, C);                        // O3
            mmTN(Bm, C, L);  m2aa(L, res + 27);     // joint 15 = Y12^T O3
        } else {
            gs6(my + 0,  A); gs6(my + 66, Bm);      // Y1, O1
            mmTN(A, Bm, L);  m2aa(L, res + 0);      // joint 4  = Y1^T O1
            gs6(my + 6,  A); gs6(my + 72, Bm);      // Y2, O2
            mmTN(A, Bm, L);  m2aa(L, res + 3);      // joint 5  = Y2^T O2
            gs6(my + 36, A); gs6(my + 48, Bm);      // Y13, Y16 (Y16 kept)
            mmTN(A, Bm, L);  m2aa(L, res + 6);      // joint 16 = Y13^T Y16
            gs6(my + 54, A);                        // Y17 (kept)
            gs6(my + 42, C);                        // Y14
            mmTN(C, A, L);   m2aa(L, res + 9);      // joint 17 = Y14^T Y17
            gs6(my + 84, C);                        // O4
            mmTN(Bm, C, L);  m2aa(L, res + 12);     // joint 18 = Y16^T O4
            gs6(my + 90, C);                        // O5
            mmTN(A, C, L);   m2aa(L, res + 15);     // joint 19 = Y17^T O5
        }
    }
    __syncthreads();   // all input reads complete

    // ---- Store phase: disjoint smem writes per role; outputs at my[0..71] ----
    if (valid) {
        if (role == 0) {
            #pragma unroll
            for (int k = 0; k < 12; k++) my[k] = res[k];           // joints 0..3
            my[18] = res[12]; my[19] = res[13]; my[20] = res[14];  // joint 6
            my[21] = 0.f; my[22] = 0.f; my[23] = 0.f;              // joint 7
            my[24] = 0.f; my[25] = 0.f; my[26] = 0.f;              // joint 8
            my[27] = res[15]; my[28] = res[16]; my[29] = res[17];  // joint 9
            my[30] = 0.f; my[31] = 0.f; my[32] = 0.f;              // joint 10
            my[33] = 0.f; my[34] = 0.f; my[35] = 0.f;              // joint 11
            #pragma unroll
            for (int k = 0; k < 12; k++) my[36 + k] = res[18 + k]; // joints 12..15
        } else {
            my[12] = res[0];  my[13] = res[1];  my[14] = res[2];   // joint 4
            my[15] = res[3];  my[16] = res[4];  my[17] = res[5];   // joint 5
            my[48] = res[6];  my[49] = res[7];  my[50] = res[8];   // joint 16
            my[51] = res[9];  my[52] = res[10]; my[53] = res[11];  // joint 17
            my[54] = res[12]; my[55] = res[13]; my[56] = res[14];  // joint 18
            my[57] = res[15]; my[58] = res[16]; my[59] = res[17];  // joint 19
            #pragma unroll
            for (int k = 60; k < 72; k++) my[k] = 0.f;             // joints 20..23
        }
    }
    __syncthreads();

    // ---- Coalesced f4 stores, branch-free (zeros already in smem) ----
    {
        float4* dst = (float4*)(out + (size_t)base * 72);
        int ntot = cnt * 18;
        #pragma unroll
        for (int k = 0; k < 9; k++) {
            int j = k * THREADS + tid;
            if (j < ntot) {
                const float2* p = (const float2*)(sm + (j / 18) * STRIDE + (j % 18) * 4);
                float2 a = p[0], b = p[1];
                dst[j] = make_float4(a.x, a.y, b.x, b.y);
            }
        }
    }
}

extern "C" void kernel_launch(void* const* d_in, const int* in_sizes, int n_in,
                              void* d_out, int out_size) {
    const float* glb = (const float*)d_in[0];   // [BT,10,6]
    const float* ori = (const float*)d_in[1];   // [BT,6,6]
    float* out = (float*)d_out;                 // [BT,24,3]
    int n_items = in_sizes[0] / 60;
    int blocks = (n_items + ITEMS_PER_BLOCK - 1) / ITEMS_PER_BLOCK;
    pose_kernel<<<blocks, THREADS>>>(glb, ori, out, n_items);
}

// round 11
// speedup vs baseline: 3.8083x; 1.1852x over previous
#include <cuda_runtime.h>

// glb_reduced_6d: [BT, 10, 6] float (d_in[0]) -> 60 floats/item
// orientation_6d: [BT, 6, 6]  float (d_in[1]) -> 36 floats/item
// out:            [BT, 24, 3] float           -> 72 floats/item
//
// Block = 128 threads / 64 items. Warp w: role = w&1, item = (w>>1)*32 + lane.
// Role 0: joints {0,3,6,9,12,13,14,15}; role 1: {1,2,4,5,16,17,18,19} + tail zeros.
// Slot stride 98 floats: 8B-aligned slots, even offsets -> LDS.64, conflict-free.

#define STRIDE 98
#define ITEMS_PER_BLOCK 64
#define THREADS 128

__device__ __forceinline__ float fast_atan2p(float n, float w) {
    // atan2(n, w) with n >= 0; result in [0, pi]. ~1e-5 rad accuracy.
    float aw = fabsf(w);
    bool sw = n > aw;
    float num = sw ? aw : n;
    float den = sw ? n : aw;
    float r = __fdividef(num, den);
    float x2 = r * r;
    float p = -0.0117212f;
    p = fmaf(p, x2, 0.05265332f);
    p = fmaf(p, x2, -0.11643287f);
    p = fmaf(p, x2, 0.19354346f);
    p = fmaf(p, x2, -0.33262347f);
    p = fmaf(p, x2, 0.99997726f);
    float a = r * p;
    if (sw) a = 1.57079632679f - a;
    if (w < 0.f) a = 3.14159265359f - a;
    return a;
}

// d must be 8-byte aligned (even float offset in an 8B-aligned slot)
__device__ __forceinline__ void gs6(const float* d, float* __restrict__ m) {
    const float2* q = (const float2*)d;
    float2 q0 = q[0], q1 = q[1], q2 = q[2];
    float x = q0.x, y = q0.y, z = q1.x;
    float u = q1.y, v = q2.x, w = q2.y;
    float inv = rsqrtf(x * x + y * y + z * z);
    float b1x = x * inv, b1y = y * inv, b1z = z * inv;
    float dot = b1x * u + b1y * v + b1z * w;
    float c2x = u - dot * b1x, c2y = v - dot * b1y, c2z = w - dot * b1z;
    float inv2 = rsqrtf(c2x * c2x + c2y * c2y + c2z * c2z);
    float b2x = c2x * inv2, b2y = c2y * inv2, b2z = c2z * inv2;
    m[0] = b1x; m[1] = b1y; m[2] = b1z;
    m[3] = b2x; m[4] = b2y; m[5] = b2z;
    m[6] = b1y * b2z - b1z * b2y;
    m[7] = b1z * b2x - b1x * b2z;
    m[8] = b1x * b2y - b1y * b2x;
}

__device__ __forceinline__ void mmTN(const float* __restrict__ A, const float* __restrict__ B,
                                     float* __restrict__ C) {
    #pragma unroll
    for (int r = 0; r < 3; r++)
        #pragma unroll
        for (int c = 0; c < 3; c++)
            C[r * 3 + c] = A[0 * 3 + r] * B[0 * 3 + c]
                         + A[1 * 3 + r] * B[1 * 3 + c]
                         + A[2 * 3 + r] * B[2 * 3 + c];
}

__device__ __forceinline__ void m2aa(const float* __restrict__ m, float* __restrict__ ob) {
    float m00 = m[0], m01 = m[1], m02 = m[2];
    float m10 = m[3], m11 = m[4], m12 = m[5];
    float m20 = m[6], m21 = m[7], m22 = m[8];
    float t0 = fmaxf(1.f + m00 + m11 + m22, 0.f);
    float t1 = fmaxf(1.f + m00 - m11 - m22, 0.f);
    float t2 = fmaxf(1.f - m00 + m11 - m22, 0.f);
    float t3 = fmaxf(1.f - m00 - m11 + m22, 0.f);
    // Branchless 2-level argmax tournament; strict > preserves argmax
    // first-max-on-tie semantics.
    bool a01 = t1 > t0;
    bool a23 = t3 > t2;
    float ta = a01 ? t1 : t0;
    float tc = a23 ? t3 : t2;
    bool ab  = tc > ta;
    float qw = ab ? (a23 ? m10 - m01 : m02 - m20) : (a01 ? m21 - m12 : t0);
    float qx = ab ? (a23 ? m20 + m02 : m10 + m01) : (a01 ? t1        : m21 - m12);
    float qy = ab ? (a23 ? m21 + m12 : t2       ) : (a01 ? m10 + m01 : m02 - m20);
    float qz = ab ? (a23 ? t3        : m12 + m21) : (a01 ? m02 + m20 : m10 - m01);
    // 1/(2*max(qa,0.1)) cancels (unit quat: sin(half)=|vec|):
    // out = vec_raw * (2*atan2(|vec_raw|, qw_raw) / |vec_raw|)
    float s = qx * qx + qy * qy + qz * qz;
    s = fmaxf(s, 1e-24f);
    float inv_n = rsqrtf(s);
    float n = s * inv_n;
    float half = fast_atan2p(n, qw);
    float factor = 2.f * half * inv_n;
    ob[0] = qx * factor; ob[1] = qy * factor; ob[2] = qz * factor;
}

__global__ void __launch_bounds__(THREADS, 5)
pose_kernel(const float* __restrict__ glb, const float* __restrict__ ori,
            float* __restrict__ out, int n_items)
{
    __shared__ float sm[ITEMS_PER_BLOCK * STRIDE];
    const int tid = threadIdx.x;
    const int warp = tid >> 5;
    const int lane = tid & 31;
    const int base = blockIdx.x * ITEMS_PER_BLOCK;
    int cnt = n_items - base;
    if (cnt > ITEMS_PER_BLOCK) cnt = ITEMS_PER_BLOCK;
    if (cnt < 0) cnt = 0;

    // ---- Stage glb: 64 items x 15 f4, coalesced; slot floats [0..59] ----
    // Incremental div/mod: j = k*128 + tid; 128 = 8*15 + 8.
    {
        const float4* src = (const float4*)(glb + (size_t)base * 60);
        int ntot = cnt * 15;
        int r = tid % 15;
        int addr = (tid / 15) * STRIDE + r * 4;
        #pragma unroll
        for (int k = 0; k < 8; k++) {
            int j = k * THREADS + tid;
            if (j < ntot) {
                float4 v = src[j];
                float2* p = (float2*)(sm + addr);
                p[0] = make_float2(v.x, v.y);
                p[1] = make_float2(v.z, v.w);
            }
            r += 8; addr += 8 * STRIDE + 32;
            if (r >= 15) { r -= 15; addr += STRIDE - 60; }
        }
    }
    // ---- Stage ori: 64 items x 9 f4; slot floats [60..95]; 128 = 14*9 + 2 ----
    {
        const float4* src = (const float4*)(ori + (size_t)base * 36);
        int ntot = cnt * 9;
        int r = tid % 9;
        int addr = (tid / 9) * STRIDE + 60 + r * 4;
        #pragma unroll
        for (int k = 0; k < 5; k++) {
            int j = k * THREADS + tid;
            if (j < ntot) {
                float4 v = src[j];
                float2* p = (float2*)(sm + addr);
                p[0] = make_float2(v.x, v.y);
                p[1] = make_float2(v.z, v.w);
            }
            r += 2; addr += 14 * STRIDE + 8;
            if (r >= 9) { r -= 9; addr += STRIDE - 36; }
        }
    }
    __syncthreads();

    const int role = warp & 1;
    const int item_local = (warp >> 1) * 32 + lane;
    float* my = sm + item_local * STRIDE;
    const bool valid = item_local < cnt;

    // ---- Compute phase: smem READ-ONLY; results in registers ----
    float res[24];
    if (valid) {
        float A[9], B9[9], C9[9], D9[9], L[9];
        if (role == 0) {
            gs6(my + 60, A);  m2aa(A, res + 0);      // joint 0 (root)
            gs6(my + 12, A);  m2aa(A, res + 3);      // joint 3 (Y3, kept)
            gs6(my + 18, B9);                        // Y6
            mmTN(A, B9, L);   m2aa(L, res + 6);      // joint 6  = Y3^T Y6
            gs6(my + 24, C9);                        // Y9
            mmTN(B9, C9, L);  m2aa(L, res + 9);      // joint 9  = Y6^T Y9
            gs6(my + 30, D9);                        // Y12 (kept)
            mmTN(C9, D9, L);  m2aa(L, res + 12);     // joint 12 = Y9^T Y12
            gs6(my + 36, A);                         // Y13
            mmTN(C9, A, L);   m2aa(L, res + 15);     // joint 13 = Y9^T Y13
            gs6(my + 42, A);                         // Y14
            mmTN(C9, A, L);   m2aa(L, res + 18);     // joint 14 = Y9^T Y14
            gs6(my + 78, A);                         // O3
            mmTN(D9, A, L);   m2aa(L, res + 21);     // joint 15 = Y12^T O3
        } else {
            gs6(my + 0,  A);  m2aa(A, res + 0);      // joint 1 (Y1)
            gs6(my + 66, B9);                        // O1
            mmTN(A, B9, L);   m2aa(L, res + 3);      // joint 4  = Y1^T O1
            gs6(my + 6,  A);  m2aa(A, res + 6);      // joint 2 (Y2)
            gs6(my + 72, B9);                        // O2
            mmTN(A, B9, L);   m2aa(L, res + 9);      // joint 5  = Y2^T O2
            gs6(my + 36, A);  gs6(my + 48, B9);      // Y13, Y16 (kept)
            mmTN(A, B9, L);   m2aa(L, res + 12);     // joint 16 = Y13^T Y16
            gs6(my + 42, A);  gs6(my + 54, C9);      // Y14, Y17 (kept)
            mmTN(A, C9, L);   m2aa(L, res + 15);     // joint 17 = Y14^T Y17
            gs6(my + 84, A);                         // O4
            mmTN(B9, A, L);   m2aa(L, res + 18);     // joint 18 = Y16^T O4
            gs6(my + 90, A);                         // O5
            mmTN(C9, A, L);   m2aa(L, res + 21);     // joint 19 = Y17^T O5
        }
    }
    __syncthreads();   // all input reads complete

    // ---- Store phase: disjoint smem writes per role; outputs at my[0..71] ----
    if (valid) {
        if (role == 0) {
            my[0]  = res[0];  my[1]  = res[1];  my[2]  = res[2];   // joint 0
            my[9]  = res[3];  my[10] = res[4];  my[11] = res[5];   // joint 3
            my[18] = res[6];  my[19] = res[7];  my[20] = res[8];   // joint 6
            my[21] = 0.f; my[22] = 0.f; my[23] = 0.f;              // joint 7
            my[24] = 0.f; my[25] = 0.f; my[26] = 0.f;              // joint 8
            my[27] = res[9];  my[28] = res[10]; my[29] = res[11];  // joint 9
            my[30] = 0.f; my[31] = 0.f; my[32] = 0.f;              // joint 10
            my[33] = 0.f; my[34] = 0.f; my[35] = 0.f;              // joint 11
            my[36] = res[12]; my[37] = res[13]; my[38] = res[14];  // joint 12
            my[39] = res[15]; my[40] = res[16]; my[41] = res[17];  // joint 13
            my[42] = res[18]; my[43] = res[19]; my[44] = res[20];  // joint 14
            my[45] = res[21]; my[46] = res[22]; my[47] = res[23];  // joint 15
        } else {
            my[3]  = res[0];  my[4]  = res[1];  my[5]  = res[2];   // joint 1
            my[6]  = res[6];  my[7]  = res[7];  my[8]  = res[8];   // joint 2
            my[12] = res[3];  my[13] = res[4];  my[14] = res[5];   // joint 4
            my[15] = res[9];  my[16] = res[10]; my[17] = res[11];  // joint 5
            my[48] = res[12]; my[49] = res[13]; my[50] = res[14];  // joint 16
            my[51] = res[15]; my[52] = res[16]; my[53] = res[17];  // joint 17
            my[54] = res[18]; my[55] = res[19]; my[56] = res[20];  // joint 18
            my[57] = res[21]; my[58] = res[22]; my[59] = res[23];  // joint 19
            #pragma unroll
            for (int k = 60; k < 72; k++) my[k] = 0.f;             // joints 20..23
        }
    }
    __syncthreads();

    // ---- Coalesced f4 stores; incremental addressing (128 = 7*18 + 2) ----
    {
        float4* dst = (float4*)(out + (size_t)base * 72);
        int ntot = cnt * 18;
        int r = tid % 18;
        int addr = (tid / 18) * STRIDE + r * 4;
        #pragma unroll
        for (int k = 0; k < 9; k++) {
            int j = k * THREADS + tid;
            if (j < ntot) {
                const float2* p = (const float2*)(sm + addr);
                float2 a = p[0], b = p[1];
                dst[j] = make_float4(a.x, a.y, b.x, b.y);
            }
            r += 2; addr += 7 * STRIDE + 8;
            if (r >= 18) { r -= 18; addr += STRIDE - 72; }
        }
    }
}

extern "C" void kernel_launch(void* const* d_in, const int* in_sizes, int n_in,
                              void* d_out, int out_size) {
    const float* glb = (const float*)d_in[0];   // [BT,10,6]
    const float* ori = (const float*)d_in[1];   // [BT,6,6]
    float* out = (float*)d_out;                 // [BT,24,3]
    int n_items = in_sizes[0] / 60;
    int blocks = (n_items + ITEMS_PER_BLOCK - 1) / ITEMS_PER_BLOCK;
    pose_kernel<<<blocks, THREADS>>>(glb, ori, out, n_items);
}